// round 12
// baseline (speedup 1.0000x reference)
#include <cuda_runtime.h>
#include <cuda_bf16.h>
#include <cstdint>
#include <math_constants.h>

// ---------------------------------------------------------------------------
// AdaptiveAttention: B=2, S=2048, HS=1024, NH=16, HD=64, NP=8
// Round 12: pre-split bf16 hi/lo operands from the QKV epilogue + single
//           fused scores/softmax/context kernel with online LSE stats.
// ---------------------------------------------------------------------------

constexpr int cB = 2, cS = 2048, cHS = 1024, cNH = 16, cNP = 8, cHD = 64;
constexpr float cSCALE = 0.125f;
constexpr long OUT_ELEMS  = (long)cB * cS * cHS;
constexpr long ATTN_ELEMS = (long)cB * cNH * cS * cS;

__device__ __nv_bfloat16 g_Qh[(long)cB * cNH * cS * cHD];
__device__ __nv_bfloat16 g_Ql[(long)cB * cNH * cS * cHD];
__device__ __nv_bfloat16 g_Kh[(long)cB * cNH * cS * cHD];
__device__ __nv_bfloat16 g_Kl[(long)cB * cNH * cS * cHD];
__device__ __nv_bfloat16 g_Vth[(long)cB * cNH * cHD * cS];  // transposed [bh,d,s]
__device__ __nv_bfloat16 g_Vtl[(long)cB * cNH * cHD * cS];
__device__ float g_ctx[(long)cB * cS * cHS];
__device__ float g_pat[cB * cNH];
__device__ float g_WT[4L * cHS * cHS];
__device__ float g_qpart[32 * cHS];
__device__ float g_attn_fallback[ATTN_ELEMS];

// ---------------------------------------------------------------------------
__device__ __forceinline__ uint32_t smem_u32(const void* p) {
    uint32_t a;
    asm("{ .reg .u64 t; cvta.to.shared.u64 t, %1; cvt.u32.u64 %0, t; }" : "=r"(a) : "l"(p));
    return a;
}
#define CP_ASYNC16(dst, src) \
    asm volatile("cp.async.cg.shared.global [%0], [%1], 16;" :: "r"(dst), "l"(src))
#define CP_COMMIT() asm volatile("cp.async.commit_group;")
#define CP_WAIT(n)  asm volatile("cp.async.wait_group %0;" :: "n"(n))

__device__ __forceinline__ void mma_bf16(float c[4], const uint32_t a[4], const uint32_t b[2]) {
    asm volatile(
        "mma.sync.aligned.m16n8k16.row.col.f32.bf16.bf16.f32 "
        "{%0,%1,%2,%3}, {%4,%5,%6,%7}, {%8,%9}, {%0,%1,%2,%3};"
        : "+f"(c[0]), "+f"(c[1]), "+f"(c[2]), "+f"(c[3])
        : "r"(a[0]), "r"(a[1]), "r"(a[2]), "r"(a[3]), "r"(b[0]), "r"(b[1]));
}
__device__ __forceinline__ void ldsm_x4(uint32_t& r0, uint32_t& r1, uint32_t& r2, uint32_t& r3,
                                        uint32_t addr) {
    asm volatile("ldmatrix.sync.aligned.m8n8.x4.shared.b16 {%0,%1,%2,%3}, [%4];"
                 : "=r"(r0), "=r"(r1), "=r"(r2), "=r"(r3) : "r"(addr));
}

__device__ __forceinline__ uint32_t pk2(__nv_bfloat16 a, __nv_bfloat16 b) {
    __nv_bfloat162 t;
    t.x = a; t.y = b;
    return *(uint32_t*)&t;
}
__device__ __forceinline__ void split4_pk(float4 v, uint2& hp, uint2& lp) {
    __nv_bfloat16 h0 = __float2bfloat16_rn(v.x);
    __nv_bfloat16 h1 = __float2bfloat16_rn(v.y);
    __nv_bfloat16 h2 = __float2bfloat16_rn(v.z);
    __nv_bfloat16 h3 = __float2bfloat16_rn(v.w);
    __nv_bfloat16 l0 = __float2bfloat16_rn(v.x - __bfloat162float(h0));
    __nv_bfloat16 l1 = __float2bfloat16_rn(v.y - __bfloat162float(h1));
    __nv_bfloat16 l2 = __float2bfloat16_rn(v.z - __bfloat162float(h2));
    __nv_bfloat16 l3 = __float2bfloat16_rn(v.w - __bfloat162float(h3));
    hp.x = pk2(h0, h1); hp.y = pk2(h2, h3);
    lp.x = pk2(l0, l1); lp.y = pk2(l2, l3);
}
__device__ __forceinline__ void split1(float x, __nv_bfloat16& h, __nv_bfloat16& l) {
    h = __float2bfloat16_rn(x);
    l = __float2bfloat16_rn(x - __bfloat162float(h));
}

// ldmatrix per-lane byte offsets (A: m16xk16 row-major; B: two n8xk16 tiles)
__device__ __forceinline__ uint32_t ldsmA_off(int lane, int rowbytes) {
    int row = (lane & 7) + (((lane >> 3) & 1) << 3);
    int k8  = (lane >> 4) & 1;
    return (uint32_t)(row * rowbytes + k8 * 16);
}
__device__ __forceinline__ uint32_t ldsmB_off(int lane, int rowbytes) {
    int row = (lane & 7) + (((lane >> 4) & 1) << 3);
    int k8  = (lane >> 3) & 1;
    return (uint32_t)(row * rowbytes + k8 * 16);
}

// ===========================================================================
// gemm_qkv: merged QKV projection; epilogue splits to bf16 hi/lo and stores
// Q/K as [bh,s,d], V transposed as [bh,d,s]. 256 thr, 128x128, K-chunk 32.
// ===========================================================================
__global__ __launch_bounds__(256)
void gemm_qkv(const float* __restrict__ A0, const float* __restrict__ A1,
              const float* __restrict__ A2, const float* __restrict__ WT,
              const float* __restrict__ b0v, const float* __restrict__ b1v,
              const float* __restrict__ b2v)
{
    extern __shared__ char smraw[];
    __nv_bfloat16* Ah = (__nv_bfloat16*)smraw;        // [2][128*40]
    const int z = blockIdx.z;
    const float* A    = z == 0 ? A0 : (z == 1 ? A1 : A2);
    const float* Bt   = WT + (size_t)z * cHS * cHS;
    const float* bias = z == 0 ? b0v : (z == 1 ? b1v : b2v);

    const int t = threadIdx.x, lane = t & 31, wid = t >> 5;
    const int wm = wid >> 1, wn = wid & 1;
    const int gid = lane >> 2, tig = lane & 3;
    const int m0 = blockIdx.y * 128, n0 = blockIdx.x * 128;

    const uint32_t uAh = smem_u32(Ah);
    const uint32_t uAl = uAh + 2 * 5120 * 2;
    const uint32_t uBh = uAh + 4 * 5120 * 2;
    const uint32_t uBl = uAh + 6 * 5120 * 2;
    const uint32_t laneA = ldsmA_off(lane, 80) + (uint32_t)(wm * 32 * 80);
    const uint32_t laneB = ldsmB_off(lane, 80) + (uint32_t)(wn * 64 * 80);

    float c[2][8][4] = {};
    float4 rA[4], rB[4];

#pragma unroll
    for (int i = 0; i < 4; i++) {
        int idx = t + i * 256, r = idx >> 3, kq = idx & 7;
        rA[i] = *(const float4*)&A[(size_t)(m0 + r) * 1024 + kq * 4];
        rB[i] = *(const float4*)&Bt[(size_t)(n0 + r) * 1024 + kq * 4];
    }
    {
        __nv_bfloat16* Al = Ah + 2 * 5120;
        __nv_bfloat16* Bh = Ah + 4 * 5120;
        __nv_bfloat16* Bl = Ah + 6 * 5120;
#pragma unroll
        for (int i = 0; i < 4; i++) {
            int idx = t + i * 256, r = idx >> 3, kq = idx & 7;
            uint2 hp, lp;
            split4_pk(rA[i], hp, lp);
            *(uint2*)&Ah[r * 40 + kq * 4] = hp;
            *(uint2*)&Al[r * 40 + kq * 4] = lp;
            split4_pk(rB[i], hp, lp);
            *(uint2*)&Bh[r * 40 + kq * 4] = hp;
            *(uint2*)&Bl[r * 40 + kq * 4] = lp;
        }
    }
    __syncthreads();

    const int T = 32;
    for (int ch = 0; ch < T; ch++) {
        const int cur = ch & 1;
        if (ch + 1 < T) {
#pragma unroll
            for (int i = 0; i < 4; i++) {
                int idx = t + i * 256, r = idx >> 3, kq = idx & 7;
                rA[i] = *(const float4*)&A[(size_t)(m0 + r) * 1024 + (ch + 1) * 32 + kq * 4];
                rB[i] = *(const float4*)&Bt[(size_t)(n0 + r) * 1024 + (ch + 1) * 32 + kq * 4];
            }
        }
        const uint32_t bufo = (uint32_t)cur * 10240;
#pragma unroll
        for (int kk = 0; kk < 2; kk++) {
            uint32_t ah[2][4], al[2][4], bh[8][2], bl[8][2];
            const uint32_t ko = (uint32_t)kk * 32;
#pragma unroll
            for (int mi = 0; mi < 2; mi++) {
                uint32_t ao = bufo + laneA + (uint32_t)(mi * 16 * 80) + ko;
                ldsm_x4(ah[mi][0], ah[mi][1], ah[mi][2], ah[mi][3], uAh + ao);
                ldsm_x4(al[mi][0], al[mi][1], al[mi][2], al[mi][3], uAl + ao);
            }
#pragma unroll
            for (int p = 0; p < 4; p++) {
                uint32_t bo = bufo + laneB + (uint32_t)(p * 16 * 80) + ko;
                ldsm_x4(bh[2*p][0], bh[2*p][1], bh[2*p+1][0], bh[2*p+1][1], uBh + bo);
                ldsm_x4(bl[2*p][0], bl[2*p][1], bl[2*p+1][0], bl[2*p+1][1], uBl + bo);
            }
#pragma unroll
            for (int mi = 0; mi < 2; mi++)
#pragma unroll
                for (int ni = 0; ni < 8; ni++) {
                    mma_bf16(c[mi][ni], al[mi], bh[ni]);
                    mma_bf16(c[mi][ni], ah[mi], bl[ni]);
                    mma_bf16(c[mi][ni], ah[mi], bh[ni]);
                }
        }
        if (ch + 1 < T) {
            __syncthreads();
            __nv_bfloat16* Ahw = Ah + (cur ^ 1) * 5120;
            __nv_bfloat16* Alw = Ah + 2 * 5120 + (cur ^ 1) * 5120;
            __nv_bfloat16* Bhw = Ah + 4 * 5120 + (cur ^ 1) * 5120;
            __nv_bfloat16* Blw = Ah + 6 * 5120 + (cur ^ 1) * 5120;
#pragma unroll
            for (int i = 0; i < 4; i++) {
                int idx = t + i * 256, r = idx >> 3, kq = idx & 7;
                uint2 hp, lp;
                split4_pk(rA[i], hp, lp);
                *(uint2*)&Ahw[r * 40 + kq * 4] = hp;
                *(uint2*)&Alw[r * 40 + kq * 4] = lp;
                split4_pk(rB[i], hp, lp);
                *(uint2*)&Bhw[r * 40 + kq * 4] = hp;
                *(uint2*)&Blw[r * 40 + kq * 4] = lp;
            }
            __syncthreads();
        }
    }

#pragma unroll
    for (int mi = 0; mi < 2; mi++)
#pragma unroll
        for (int half = 0; half < 2; half++) {
            int m = m0 + wm * 32 + mi * 16 + gid + half * 8;
            int b = m >> 11, s = m & 2047;
#pragma unroll
            for (int ni = 0; ni < 8; ni++) {
                int n = n0 + wn * 64 + ni * 8 + tig * 2;
                int h = n >> 6, d = n & 63;
                float vx = c[mi][ni][half * 2 + 0] + bias[n];
                float vy = c[mi][ni][half * 2 + 1] + bias[n + 1];
                __nv_bfloat16 hx, lx, hy, ly;
                split1(vx, hx, lx);
                split1(vy, hy, ly);
                if (z < 2) {
                    size_t off = ((size_t)(b * cNH + h) * cS + s) * cHD + d;
                    __nv_bfloat16* H = z == 0 ? g_Qh : g_Kh;
                    __nv_bfloat16* L = z == 0 ? g_Ql : g_Kl;
                    *(uint32_t*)&H[off] = pk2(hx, hy);
                    *(uint32_t*)&L[off] = pk2(lx, ly);
                } else {
                    size_t off = ((size_t)(b * cNH + h) * cHD + d) * cS + s;
                    g_Vth[off] = hx; g_Vtl[off] = lx;
                    g_Vth[off + cS] = hy; g_Vtl[off + cS] = ly;
                }
            }
        }
}

// ===========================================================================
// gemm_out: output projection (fp32 A, split in-kernel as R11). 256 thr.
// ===========================================================================
__global__ __launch_bounds__(256)
void gemm_out(const float* __restrict__ A, const float* __restrict__ Bt,
              const float* __restrict__ bias, float* __restrict__ C)
{
    extern __shared__ char smraw[];
    __nv_bfloat16* Ah = (__nv_bfloat16*)smraw;
    const int t = threadIdx.x, lane = t & 31, wid = t >> 5;
    const int wm = wid >> 1, wn = wid & 1;
    const int gid = lane >> 2, tig = lane & 3;
    const int m0 = blockIdx.y * 128, n0 = blockIdx.x * 128;

    const uint32_t uAh = smem_u32(Ah);
    const uint32_t uAl = uAh + 2 * 5120 * 2;
    const uint32_t uBh = uAh + 4 * 5120 * 2;
    const uint32_t uBl = uAh + 6 * 5120 * 2;
    const uint32_t laneA = ldsmA_off(lane, 80) + (uint32_t)(wm * 32 * 80);
    const uint32_t laneB = ldsmB_off(lane, 80) + (uint32_t)(wn * 64 * 80);

    float c[2][8][4] = {};
    float4 rA[4], rB[4];

#pragma unroll
    for (int i = 0; i < 4; i++) {
        int idx = t + i * 256, r = idx >> 3, kq = idx & 7;
        rA[i] = *(const float4*)&A[(size_t)(m0 + r) * 1024 + kq * 4];
        rB[i] = *(const float4*)&Bt[(size_t)(n0 + r) * 1024 + kq * 4];
    }
    {
        __nv_bfloat16* Al = Ah + 2 * 5120;
        __nv_bfloat16* Bh = Ah + 4 * 5120;
        __nv_bfloat16* Bl = Ah + 6 * 5120;
#pragma unroll
        for (int i = 0; i < 4; i++) {
            int idx = t + i * 256, r = idx >> 3, kq = idx & 7;
            uint2 hp, lp;
            split4_pk(rA[i], hp, lp);
            *(uint2*)&Ah[r * 40 + kq * 4] = hp;
            *(uint2*)&Al[r * 40 + kq * 4] = lp;
            split4_pk(rB[i], hp, lp);
            *(uint2*)&Bh[r * 40 + kq * 4] = hp;
            *(uint2*)&Bl[r * 40 + kq * 4] = lp;
        }
    }
    __syncthreads();

    const int T = 32;
    for (int ch = 0; ch < T; ch++) {
        const int cur = ch & 1;
        if (ch + 1 < T) {
#pragma unroll
            for (int i = 0; i < 4; i++) {
                int idx = t + i * 256, r = idx >> 3, kq = idx & 7;
                rA[i] = *(const float4*)&A[(size_t)(m0 + r) * 1024 + (ch + 1) * 32 + kq * 4];
                rB[i] = *(const float4*)&Bt[(size_t)(n0 + r) * 1024 + (ch + 1) * 32 + kq * 4];
            }
        }
        const uint32_t bufo = (uint32_t)cur * 10240;
#pragma unroll
        for (int kk = 0; kk < 2; kk++) {
            uint32_t ah[2][4], al[2][4], bh[8][2], bl[8][2];
            const uint32_t ko = (uint32_t)kk * 32;
#pragma unroll
            for (int mi = 0; mi < 2; mi++) {
                uint32_t ao = bufo + laneA + (uint32_t)(mi * 16 * 80) + ko;
                ldsm_x4(ah[mi][0], ah[mi][1], ah[mi][2], ah[mi][3], uAh + ao);
                ldsm_x4(al[mi][0], al[mi][1], al[mi][2], al[mi][3], uAl + ao);
            }
#pragma unroll
            for (int p = 0; p < 4; p++) {
                uint32_t bo = bufo + laneB + (uint32_t)(p * 16 * 80) + ko;
                ldsm_x4(bh[2*p][0], bh[2*p][1], bh[2*p+1][0], bh[2*p+1][1], uBh + bo);
                ldsm_x4(bl[2*p][0], bl[2*p][1], bl[2*p+1][0], bl[2*p+1][1], uBl + bo);
            }
#pragma unroll
            for (int mi = 0; mi < 2; mi++)
#pragma unroll
                for (int ni = 0; ni < 8; ni++) {
                    mma_bf16(c[mi][ni], al[mi], bh[ni]);
                    mma_bf16(c[mi][ni], ah[mi], bl[ni]);
                    mma_bf16(c[mi][ni], ah[mi], bh[ni]);
                }
        }
        if (ch + 1 < T) {
            __syncthreads();
            __nv_bfloat16* Ahw = Ah + (cur ^ 1) * 5120;
            __nv_bfloat16* Alw = Ah + 2 * 5120 + (cur ^ 1) * 5120;
            __nv_bfloat16* Bhw = Ah + 4 * 5120 + (cur ^ 1) * 5120;
            __nv_bfloat16* Blw = Ah + 6 * 5120 + (cur ^ 1) * 5120;
#pragma unroll
            for (int i = 0; i < 4; i++) {
                int idx = t + i * 256, r = idx >> 3, kq = idx & 7;
                uint2 hp, lp;
                split4_pk(rA[i], hp, lp);
                *(uint2*)&Ahw[r * 40 + kq * 4] = hp;
                *(uint2*)&Alw[r * 40 + kq * 4] = lp;
                split4_pk(rB[i], hp, lp);
                *(uint2*)&Bhw[r * 40 + kq * 4] = hp;
                *(uint2*)&Blw[r * 40 + kq * 4] = lp;
            }
            __syncthreads();
        }
    }

#pragma unroll
    for (int mi = 0; mi < 2; mi++)
#pragma unroll
        for (int half = 0; half < 2; half++) {
            int m = m0 + wm * 32 + mi * 16 + gid + half * 8;
#pragma unroll
            for (int ni = 0; ni < 8; ni++) {
                int n = n0 + wn * 64 + ni * 8 + tig * 2;
                float2 v;
                v.x = c[mi][ni][half * 2 + 0] + bias[n];
                v.y = c[mi][ni][half * 2 + 1] + bias[n + 1];
                *(float2*)&C[(size_t)m * 1024 + n] = v;
            }
        }
}

// ===========================================================================
// attn_fused: scores (raw write + online LSE) then softmax+context, one CTA
// per (q-tile, bh). 256 threads. Pre-split bf16 operands via cp.async.
// smem: [0,18432) Qh | [18432,36864) Ql | [36864, 36864+2*36864) K bufs
//       (phase 2 overlays p/V buffers on the K region). Total 110592 B.
// ===========================================================================
__global__ __launch_bounds__(256)
void attn_fused(const int* __restrict__ mask, float* __restrict__ attn)
{
    extern __shared__ char smraw[];
    const uint32_t uS = smem_u32(smraw);
    const uint32_t uQH = uS, uQL = uS + 18432;
    __shared__ float2 s_red[128][2];
    __shared__ float sm_m[128], sm_i[128];

    const int t = threadIdx.x, lane = t & 31, wid = t >> 5;
    const int wm = wid >> 1, wn = wid & 1;
    const int gid = lane >> 2, tig = lane & 3;
    const int bh = blockIdx.y, b = bh >> 4;
    const int q0 = blockIdx.x * 128;

    const __nv_bfloat16* Qhg = g_Qh + (size_t)bh * cS * cHD;
    const __nv_bfloat16* Qlg = g_Ql + (size_t)bh * cS * cHD;
    const __nv_bfloat16* Khg = g_Kh + (size_t)bh * cS * cHD;
    const __nv_bfloat16* Klg = g_Kl + (size_t)bh * cS * cHD;
    float* Am = attn + (size_t)bh * cS * cS;

    const uint32_t laneA144 = ldsmA_off(lane, 144) + (uint32_t)(wm * 32 * 144);
    const uint32_t laneB144 = ldsmB_off(lane, 144) + (uint32_t)(wn * 64 * 144);

    // ---------------- phase 1: scores + online stats ----------------
    // issue Q tile + K chunk 0 (one cp.async group)
#pragma unroll
    for (int i = 0; i < 4; i++) {
        int idx = t + i * 256, r = idx >> 3, q8 = idx & 7;
        CP_ASYNC16(uQH + r * 144 + q8 * 16, Qhg + (size_t)(q0 + r) * 64 + q8 * 8);
        CP_ASYNC16(uQL + r * 144 + q8 * 16, Qlg + (size_t)(q0 + r) * 64 + q8 * 8);
        CP_ASYNC16(uS + 36864 + r * 144 + q8 * 16, Khg + (size_t)r * 64 + q8 * 8);
        CP_ASYNC16(uS + 36864 + 18432 + r * 144 + q8 * 16, Klg + (size_t)r * 64 + q8 * 8);
    }
    CP_COMMIT();

    const float patv = g_pat[bh] * cSCALE;
    const size_t mbase = (size_t)b * cS * cS;
    float m4[4] = {-CUDART_INF_F, -CUDART_INF_F, -CUDART_INF_F, -CUDART_INF_F};
    float s4[4] = {0.f, 0.f, 0.f, 0.f};

    for (int n0 = 0; n0 < 16; n0++) {
        const int cur = n0 & 1;
        if (n0 + 1 < 16) {
            const uint32_t kb = uS + 36864 + (uint32_t)((n0 + 1) & 1) * 36864;
#pragma unroll
            for (int i = 0; i < 4; i++) {
                int idx = t + i * 256, r = idx >> 3, q8 = idx & 7;
                CP_ASYNC16(kb + r * 144 + q8 * 16,
                           Khg + (size_t)((n0 + 1) * 128 + r) * 64 + q8 * 8);
                CP_ASYNC16(kb + 18432 + r * 144 + q8 * 16,
                           Klg + (size_t)((n0 + 1) * 128 + r) * 64 + q8 * 8);
            }
            CP_COMMIT();
            CP_WAIT(1);
        } else {
            CP_WAIT(0);
        }
        __syncthreads();

        const uint32_t uKH = uS + 36864 + (uint32_t)cur * 36864;
        const uint32_t uKL = uKH + 18432;
        float c[2][8][4] = {};
#pragma unroll
        for (int kk = 0; kk < 4; kk++) {
            uint32_t ah[2][4], al[2][4], bh2[8][2], bl2[8][2];
            const uint32_t ko = (uint32_t)kk * 32;
#pragma unroll
            for (int mi = 0; mi < 2; mi++) {
                uint32_t ao = laneA144 + (uint32_t)(mi * 16 * 144) + ko;
                ldsm_x4(ah[mi][0], ah[mi][1], ah[mi][2], ah[mi][3], uQH + ao);
                ldsm_x4(al[mi][0], al[mi][1], al[mi][2], al[mi][3], uQL + ao);
            }
#pragma unroll
            for (int p = 0; p < 4; p++) {
                uint32_t bo = laneB144 + (uint32_t)(p * 16 * 144) + ko;
                ldsm_x4(bh2[2*p][0], bh2[2*p][1], bh2[2*p+1][0], bh2[2*p+1][1], uKH + bo);
                ldsm_x4(bl2[2*p][0], bl2[2*p][1], bl2[2*p+1][0], bl2[2*p+1][1], uKL + bo);
            }
#pragma unroll
            for (int mi = 0; mi < 2; mi++)
#pragma unroll
                for (int ni = 0; ni < 8; ni++) {
                    mma_bf16(c[mi][ni], al[mi], bh2[ni]);
                    mma_bf16(c[mi][ni], ah[mi], bl2[ni]);
                    mma_bf16(c[mi][ni], ah[mi], bh2[ni]);
                }
        }

        // epilogue: scale, mask, write raw, online LSE update
#pragma unroll
        for (int mi = 0; mi < 2; mi++)
#pragma unroll
            for (int half = 0; half < 2; half++) {
                const int g = mi * 2 + half;
                int q = q0 + wm * 32 + mi * 16 + half * 8 + gid;
                float vals[16];
                float cm = -CUDART_INF_F;
#pragma unroll
                for (int ni = 0; ni < 8; ni++) {
                    int col = n0 * 128 + wn * 64 + ni * 8 + tig * 2;
                    float2 v;
                    v.x = c[mi][ni][half * 2 + 0] * patv;
                    v.y = c[mi][ni][half * 2 + 1] * patv;
                    int2 mk = *(const int2*)&mask[mbase + (size_t)q * cS + col];
                    if (mk.x == 0) v.x = -1e9f;
                    if (mk.y == 0) v.y = -1e9f;
                    *(float2*)&Am[(size_t)q * cS + col] = v;
                    vals[ni * 2] = v.x; vals[ni * 2 + 1] = v.y;
                    cm = fmaxf(cm, fmaxf(v.x, v.y));
                }
                float mn = fmaxf(m4[g], cm);
                float acc = 0.f;
#pragma unroll
                for (int j = 0; j < 16; j++) acc += __expf(vals[j] - mn);
                s4[g] = s4[g] * __expf(m4[g] - mn) + acc;
                m4[g] = mn;
            }
        __syncthreads();
    }

    // reduce stats: quad shfl (online merge), then across wn via smem
#pragma unroll
    for (int g = 0; g < 4; g++) {
        float m = m4[g], s = s4[g];
#pragma unroll
        for (int off = 1; off <= 2; off <<= 1) {
            float mo = __shfl_xor_sync(0xffffffff, m, off);
            float so = __shfl_xor_sync(0xffffffff, s, off);
            float mn = fmaxf(m, mo);
            s = s * __expf(m - mn) + so * __expf(mo - mn);
            m = mn;
        }
        if (tig == 0) {
            int lr = wm * 32 + (g >> 1) * 16 + (g & 1) * 8 + gid;
            s_red[lr][wn] = make_float2(m, s);
        }
    }
    __syncthreads();
    if (t < 128) {
        float2 a = s_red[t][0], bb = s_red[t][1];
        float M = fmaxf(a.x, bb.x);
        float S = a.y * __expf(a.x - M) + bb.y * __expf(bb.x - M);
        sm_m[t] = M;
        sm_i[t] = 1.0f / S;
    }
    __syncthreads();

    // ---------------- phase 2: softmax + p@V ----------------
    const int h = bh & 15;
    const __nv_bfloat16* Vhg = g_Vth + (size_t)bh * cHD * cS;
    const __nv_bfloat16* Vlg = g_Vtl + (size_t)bh * cHD * cS;
    const uint32_t pbase = uS + 36864;
    const uint32_t laneA80 = ldsmA_off(lane, 80) + (uint32_t)(wm * 32 * 80);
    const uint32_t laneB80 = ldsmB_off(lane, 80) + (uint32_t)(wn * 32 * 80);

    float cc[2][4][4] = {};
    float4 rA[4];

    // chunk 0: V via cp.async, p via registers
    {
        int d = t >> 2, c4 = t & 3;
        CP_ASYNC16(pbase + 40960 + d * 80 + c4 * 16, Vhg + (size_t)d * cS + c4 * 8);
        CP_ASYNC16(pbase + 51200 + d * 80 + c4 * 16, Vlg + (size_t)d * cS + c4 * 8);
    }
    CP_COMMIT();
#pragma unroll
    for (int i = 0; i < 4; i++) {
        int idx = t + i * 256, r = idx >> 3, kq = idx & 7;
        rA[i] = *(const float4*)&Am[(size_t)(q0 + r) * cS + kq * 4];
    }
    {
        __nv_bfloat16* Ph = (__nv_bfloat16*)(smraw + 36864);
        __nv_bfloat16* Pl = (__nv_bfloat16*)(smraw + 36864 + 20480);
#pragma unroll
        for (int i = 0; i < 4; i++) {
            int idx = t + i * 256, r = idx >> 3, kq = idx & 7;
            float mm = sm_m[r], ii = sm_i[r];
            float4 p;
            p.x = __expf(rA[i].x - mm) * ii;
            p.y = __expf(rA[i].y - mm) * ii;
            p.z = __expf(rA[i].z - mm) * ii;
            p.w = __expf(rA[i].w - mm) * ii;
            *(float4*)&Am[(size_t)(q0 + r) * cS + kq * 4] = p;
            uint2 hp, lp;
            split4_pk(p, hp, lp);
            *(uint2*)&Ph[r * 40 + kq * 4] = hp;
            *(uint2*)&Pl[r * 40 + kq * 4] = lp;
        }
    }
    CP_WAIT(0);
    __syncthreads();

    const int T2 = 64;
    for (int ch = 0; ch < T2; ch++) {
        const int cur = ch & 1;
        if (ch + 1 < T2) {
            int d = t >> 2, c4 = t & 3;
            const uint32_t vb = pbase + (uint32_t)((cur ^ 1)) * 5120;
            CP_ASYNC16(vb + 40960 + d * 80 + c4 * 16,
                       Vhg + (size_t)d * cS + (ch + 1) * 32 + c4 * 8);
            CP_ASYNC16(vb + 51200 + d * 80 + c4 * 16,
                       Vlg + (size_t)d * cS + (ch + 1) * 32 + c4 * 8);
            CP_COMMIT();
#pragma unroll
            for (int i = 0; i < 4; i++) {
                int idx = t + i * 256, r = idx >> 3, kq = idx & 7;
                rA[i] = *(const float4*)&Am[(size_t)(q0 + r) * cS + (ch + 1) * 32 + kq * 4];
            }
        }
        const uint32_t uPh = pbase + (uint32_t)cur * 10240;
        const uint32_t uPl = pbase + 20480 + (uint32_t)cur * 10240;
        const uint32_t uVh = pbase + 40960 + (uint32_t)cur * 5120;
        const uint32_t uVl = pbase + 51200 + (uint32_t)cur * 5120;
#pragma unroll
        for (int kk = 0; kk < 2; kk++) {
            uint32_t ah[2][4], al[2][4], bh2[4][2], bl2[4][2];
            const uint32_t ko = (uint32_t)kk * 32;
#pragma unroll
            for (int mi = 0; mi < 2; mi++) {
                uint32_t ao = laneA80 + (uint32_t)(mi * 16 * 80) + ko;
                ldsm_x4(ah[mi][0], ah[mi][1], ah[mi][2], ah[mi][3], uPh + ao);
                ldsm_x4(al[mi][0], al[mi][1], al[mi][2], al[mi][3], uPl + ao);
            }
#pragma unroll
            for (int p = 0; p < 2; p++) {
                uint32_t bo = laneB80 + (uint32_t)(p * 16 * 80) + ko;
                ldsm_x4(bh2[2*p][0], bh2[2*p][1], bh2[2*p+1][0], bh2[2*p+1][1], uVh + bo);
                ldsm_x4(bl2[2*p][0], bl2[2*p][1], bl2[2*p+1][0], bl2[2*p+1][1], uVl + bo);
            }
#pragma unroll
            for (int mi = 0; mi < 2; mi++)
#pragma unroll
                for (int ni = 0; ni < 4; ni++) {
                    mma_bf16(cc[mi][ni], al[mi], bh2[ni]);
                    mma_bf16(cc[mi][ni], ah[mi], bl2[ni]);
                    mma_bf16(cc[mi][ni], ah[mi], bh2[ni]);
                }
        }
        __syncthreads();
        if (ch + 1 < T2) {
            __nv_bfloat16* Phw = (__nv_bfloat16*)(smraw + 36864 + (cur ^ 1) * 10240);
            __nv_bfloat16* Plw = (__nv_bfloat16*)(smraw + 36864 + 20480 + (cur ^ 1) * 10240);
#pragma unroll
            for (int i = 0; i < 4; i++) {
                int idx = t + i * 256, r = idx >> 3, kq = idx & 7;
                float mm = sm_m[r], ii = sm_i[r];
                float4 p;
                p.x = __expf(rA[i].x - mm) * ii;
                p.y = __expf(rA[i].y - mm) * ii;
                p.z = __expf(rA[i].z - mm) * ii;
                p.w = __expf(rA[i].w - mm) * ii;
                *(float4*)&Am[(size_t)(q0 + r) * cS + (ch + 1) * 32 + kq * 4] = p;
                uint2 hp, lp;
                split4_pk(p, hp, lp);
                *(uint2*)&Phw[r * 40 + kq * 4] = hp;
                *(uint2*)&Plw[r * 40 + kq * 4] = lp;
            }
            CP_WAIT(0);
            __syncthreads();
        }
    }

#pragma unroll
    for (int mi = 0; mi < 2; mi++)
#pragma unroll
        for (int half = 0; half < 2; half++) {
            int s = q0 + wm * 32 + mi * 16 + gid + half * 8;
#pragma unroll
            for (int ni = 0; ni < 4; ni++) {
                int n = wn * 32 + ni * 8 + tig * 2;
                float2 v;
                v.x = cc[mi][ni][half * 2 + 0];
                v.y = cc[mi][ni][half * 2 + 1];
                *(float2*)&g_ctx[((size_t)(b * cS + s)) * cHS + h * cHD + n] = v;
            }
        }
}

// ===========================================================================
// Weight transpose + pattern selector (unchanged)
// ===========================================================================
__global__ void transpose_w(const float* __restrict__ W0, const float* __restrict__ W1,
                            const float* __restrict__ W2, const float* __restrict__ W3)
{
    __shared__ float tile[32][33];
    const float* W = blockIdx.z == 0 ? W0 : blockIdx.z == 1 ? W1 : blockIdx.z == 2 ? W2 : W3;
    float* O = g_WT + (size_t)blockIdx.z * cHS * cHS;
    int x = blockIdx.x * 32 + threadIdx.x;
    int y0 = blockIdx.y * 32;
#pragma unroll
    for (int i = 0; i < 4; i++)
        tile[threadIdx.y + i * 8][threadIdx.x] = W[(size_t)(y0 + threadIdx.y + i * 8) * cHS + x];
    __syncthreads();
    int nx = blockIdx.y * 32 + threadIdx.x;
    int ny0 = blockIdx.x * 32;
#pragma unroll
    for (int i = 0; i < 4; i++)
        O[(size_t)(ny0 + threadIdx.y + i * 8) * cHS + nx] = tile[threadIdx.x][threadIdx.y + i * 8];
}

__global__ void qmean_partial(const float* __restrict__ query)
{
    const int b = blockIdx.y, tile = blockIdx.x;
    const int t = threadIdx.x;
    const int r0 = tile * 128;
    float s1 = 0.f, s2 = 0.f;
    for (int r = 0; r < 128; r++) {
        const float* base = query + ((size_t)b * cS + r0 + r) * cHS;
        s1 += base[t];
        s2 += base[t + 512];
    }
    g_qpart[(b * 16 + tile) * cHS + t] = s1;
    g_qpart[(b * 16 + tile) * cHS + t + 512] = s2;
}

__global__ __launch_bounds__(512)
void pattern_kernel(const float* __restrict__ Wp1, const float* __restrict__ bp1,
                    const float* __restrict__ Wp2, const float* __restrict__ bp2,
                    const float* __restrict__ patterns)
{
    const int b = blockIdx.x;
    const int t = threadIdx.x;
    __shared__ float qm[cHS];
    __shared__ float hb[cHS / 2];
    __shared__ float pw[cNP];
    for (int c = t; c < cHS; c += 512) {
        float s = 0.f;
        for (int p = 0; p < 16; p++) s += g_qpart[(b * 16 + p) * cHS + c];
        qm[c] = s * (1.0f / cS);
    }
    __syncthreads();
    {
        float a = bp1[t];
        for (int c = 0; c < cHS; c++) a += qm[c] * Wp1[c * (cHS / 2) + t];
        hb[t] = fmaxf(a, 0.f);
    }
    __syncthreads();
    __shared__ float lg[cNP];
    if (t < cNP) {
        float a = bp2[t];
        for (int j = 0; j < cHS / 2; j++) a += hb[j] * Wp2[j * cNP + t];
        lg[t] = a;
    }
    __syncthreads();
    if (t == 0) {
        float mx = lg[0];
        for (int p = 1; p < cNP; p++) mx = fmaxf(mx, lg[p]);
        float s = 0.f;
        for (int p = 0; p < cNP; p++) { pw[p] = __expf(lg[p] - mx); s += pw[p]; }
        float inv = 1.0f / s;
        for (int p = 0; p < cNP; p++) pw[p] *= inv;
    }
    __syncthreads();
    if (t < cNH) {
        float a = 0.f;
        for (int p = 0; p < cNP; p++) a += pw[p] * patterns[p * cNH + t];
        g_pat[b * cNH + t] = a;
    }
}

// ===========================================================================
// kernel_launch
// ===========================================================================
extern "C" void kernel_launch(void* const* d_in, const int* in_sizes, int n_in,
                              void* d_out, int out_size)
{
    const float* query = (const float*)d_in[0];
    const float* key   = (const float*)d_in[1];
    const float* value = (const float*)d_in[2];
    const int*   mask  = (const int*)d_in[3];
    const float* Wq  = (const float*)d_in[4];  const float* bq  = (const float*)d_in[5];
    const float* Wk  = (const float*)d_in[6];  const float* bk  = (const float*)d_in[7];
    const float* Wv  = (const float*)d_in[8];  const float* bv  = (const float*)d_in[9];
    const float* Wo  = (const float*)d_in[10]; const float* bo  = (const float*)d_in[11];
    const float* Wp1 = (const float*)d_in[12]; const float* bp1 = (const float*)d_in[13];
    const float* Wp2 = (const float*)d_in[14]; const float* bp2 = (const float*)d_in[15];
    const float* patterns = (const float*)d_in[16];
    float* out = (float*)d_out;

    void *pCtx, *pWT;
    cudaGetSymbolAddress(&pCtx, g_ctx);
    cudaGetSymbolAddress(&pWT, g_WT);
    const float* WT = (const float*)pWT;

    float* attn;
    if ((long)out_size >= OUT_ELEMS + ATTN_ELEMS) {
        attn = out + OUT_ELEMS;
    } else {
        void* pa;
        cudaGetSymbolAddress(&pa, g_attn_fallback);
        attn = (float*)pa;
    }

    const int SM_GEMM  = 8 * 5120 * 2;   // 81920
    const int SM_FUSED = 110592;
    cudaFuncSetAttribute(gemm_qkv,  cudaFuncAttributeMaxDynamicSharedMemorySize, SM_GEMM);
    cudaFuncSetAttribute(gemm_out,  cudaFuncAttributeMaxDynamicSharedMemorySize, SM_GEMM);
    cudaFuncSetAttribute(attn_fused, cudaFuncAttributeMaxDynamicSharedMemorySize, SM_FUSED);

    // 1. pattern selector
    qmean_partial<<<dim3(16, cB), 512>>>(query);
    pattern_kernel<<<cB, 512>>>(Wp1, bp1, Wp2, bp2, patterns);

    // 2. transpose weights
    transpose_w<<<dim3(32, 32, 4), dim3(32, 8)>>>(Wq, Wk, Wv, Wo);

    // 3. merged QKV projection -> pre-split bf16 hi/lo (V transposed)
    dim3 gProj(cHS / 128, (cB * cS) / 128, 3);
    gemm_qkv<<<gProj, 256, SM_GEMM>>>(query, key, value, WT, bq, bk, bv);

    // 4. fused scores + softmax + context
    dim3 gAttn(cS / 128, cB * cNH);  // (16, 32)
    attn_fused<<<gAttn, 256, SM_FUSED>>>(mask, attn);

    // 5. output projection
    dim3 gOut(cHS / 128, (cB * cS) / 128);
    gemm_out<<<gOut, 256, SM_GEMM>>>((const float*)pCtx, WT + 3L * cHS * cHS, bo, out);
}

// round 13
// speedup vs baseline: 1.0561x; 1.0561x over previous
#include <cuda_runtime.h>
#include <cuda_bf16.h>
#include <cstdint>
#include <math_constants.h>

// ---------------------------------------------------------------------------
// AdaptiveAttention: B=2, S=2048, HS=1024, NH=16, HD=64, NP=8
// Round 13: R11 kernel structure + globally pre-split bf16 hi/lo operands and
//           cp.async mainloops (no register staging / in-loop splitting).
// ---------------------------------------------------------------------------

constexpr int cB = 2, cS = 2048, cHS = 1024, cNH = 16, cNP = 8, cHD = 64;
constexpr float cSCALE = 0.125f;
constexpr long OUT_ELEMS  = (long)cB * cS * cHS;
constexpr long ATTN_ELEMS = (long)cB * cNH * cS * cS;
constexpr long QKV_ELEMS  = (long)cB * cNH * cS * cHD;   // 4,194,304

__device__ __nv_bfloat16 g_inh[3L * cB * cS * cHS];
__device__ __nv_bfloat16 g_inl[3L * cB * cS * cHS];
__device__ __nv_bfloat16 g_WTh[4L * cHS * cHS];
__device__ __nv_bfloat16 g_WTl[4L * cHS * cHS];
__device__ __nv_bfloat16 g_Qh[QKV_ELEMS], g_Ql[QKV_ELEMS];
__device__ __nv_bfloat16 g_Kh[QKV_ELEMS], g_Kl[QKV_ELEMS];
__device__ float g_V[QKV_ELEMS];                         // [bh,s,d] fp32
__device__ __nv_bfloat16 g_Vth[QKV_ELEMS], g_Vtl[QKV_ELEMS];  // [bh,d,s]
__device__ __nv_bfloat16 g_ctxh[OUT_ELEMS], g_ctxl[OUT_ELEMS];
__device__ float g_pat[cB * cNH];
__device__ float g_qpart[32 * cHS];
__device__ float2 g_pstats[(long)cB * cNH * cS * 16];
__device__ float2 g_rowstats[(long)cB * cNH * cS];
__device__ float g_attn_fallback[ATTN_ELEMS];

// ---------------------------------------------------------------------------
__device__ __forceinline__ uint32_t smem_u32(const void* p) {
    uint32_t a;
    asm("{ .reg .u64 t; cvta.to.shared.u64 t, %1; cvt.u32.u64 %0, t; }" : "=r"(a) : "l"(p));
    return a;
}
#define CP_ASYNC16(dst, src) \
    asm volatile("cp.async.cg.shared.global [%0], [%1], 16;" :: "r"(dst), "l"(src))
#define CP_COMMIT() asm volatile("cp.async.commit_group;")
#define CP_WAIT(n)  asm volatile("cp.async.wait_group %0;" :: "n"(n))

__device__ __forceinline__ void mma_bf16(float c[4], const uint32_t a[4], const uint32_t b[2]) {
    asm volatile(
        "mma.sync.aligned.m16n8k16.row.col.f32.bf16.bf16.f32 "
        "{%0,%1,%2,%3}, {%4,%5,%6,%7}, {%8,%9}, {%0,%1,%2,%3};"
        : "+f"(c[0]), "+f"(c[1]), "+f"(c[2]), "+f"(c[3])
        : "r"(a[0]), "r"(a[1]), "r"(a[2]), "r"(a[3]), "r"(b[0]), "r"(b[1]));
}
__device__ __forceinline__ void ldsm_x4(uint32_t& r0, uint32_t& r1, uint32_t& r2, uint32_t& r3,
                                        uint32_t addr) {
    asm volatile("ldmatrix.sync.aligned.m8n8.x4.shared.b16 {%0,%1,%2,%3}, [%4];"
                 : "=r"(r0), "=r"(r1), "=r"(r2), "=r"(r3) : "r"(addr));
}
__device__ __forceinline__ uint32_t pk2(__nv_bfloat16 a, __nv_bfloat16 b) {
    __nv_bfloat162 t;
    t.x = a; t.y = b;
    return *(uint32_t*)&t;
}
__device__ __forceinline__ void split4_pk(float4 v, uint2& hp, uint2& lp) {
    __nv_bfloat16 h0 = __float2bfloat16_rn(v.x);
    __nv_bfloat16 h1 = __float2bfloat16_rn(v.y);
    __nv_bfloat16 h2 = __float2bfloat16_rn(v.z);
    __nv_bfloat16 h3 = __float2bfloat16_rn(v.w);
    __nv_bfloat16 l0 = __float2bfloat16_rn(v.x - __bfloat162float(h0));
    __nv_bfloat16 l1 = __float2bfloat16_rn(v.y - __bfloat162float(h1));
    __nv_bfloat16 l2 = __float2bfloat16_rn(v.z - __bfloat162float(h2));
    __nv_bfloat16 l3 = __float2bfloat16_rn(v.w - __bfloat162float(h3));
    hp.x = pk2(h0, h1); hp.y = pk2(h2, h3);
    lp.x = pk2(l0, l1); lp.y = pk2(l2, l3);
}
__device__ __forceinline__ void split1(float x, __nv_bfloat16& h, __nv_bfloat16& l) {
    h = __float2bfloat16_rn(x);
    l = __float2bfloat16_rn(x - __bfloat162float(h));
}
__device__ __forceinline__ uint32_t ldsmA_off(int lane, int rowbytes) {
    int row = (lane & 7) + (((lane >> 3) & 1) << 3);
    int k8  = (lane >> 4) & 1;
    return (uint32_t)(row * rowbytes + k8 * 16);
}
__device__ __forceinline__ uint32_t ldsmB_off(int lane, int rowbytes) {
    int row = (lane & 7) + (((lane >> 4) & 1) << 3);
    int k8  = (lane >> 3) & 1;
    return (uint32_t)(row * rowbytes + k8 * 16);
}

// ===========================================================================
// presplit_in: query/key/value fp32 -> bf16 hi/lo (row-major [3][4096][1024])
// ===========================================================================
__global__ __launch_bounds__(256)
void presplit_in(const float* __restrict__ q, const float* __restrict__ k,
                 const float* __restrict__ v)
{
    const int z = blockIdx.y;
    const float* src = z == 0 ? q : (z == 1 ? k : v);
    size_t idx = (size_t)blockIdx.x * 256 + threadIdx.x;  // float4 index, 0..1048575
    float4 val = *(const float4*)&src[idx * 4];
    uint2 hp, lp;
    split4_pk(val, hp, lp);
    size_t off = (size_t)z * (cB * cS * cHS) + idx * 4;
    *(uint2*)&g_inh[off] = hp;
    *(uint2*)&g_inl[off] = lp;
}

// ===========================================================================
// transpose_w: W[k][n] fp32 -> WTh/WTl[n][k] bf16
// ===========================================================================
__global__ void transpose_w(const float* __restrict__ W0, const float* __restrict__ W1,
                            const float* __restrict__ W2, const float* __restrict__ W3)
{
    __shared__ float tile[32][33];
    const float* W = blockIdx.z == 0 ? W0 : blockIdx.z == 1 ? W1 : blockIdx.z == 2 ? W2 : W3;
    __nv_bfloat16* Oh = g_WTh + (size_t)blockIdx.z * cHS * cHS;
    __nv_bfloat16* Ol = g_WTl + (size_t)blockIdx.z * cHS * cHS;
    int x = blockIdx.x * 32 + threadIdx.x;
    int y0 = blockIdx.y * 32;
#pragma unroll
    for (int i = 0; i < 4; i++)
        tile[threadIdx.y + i * 8][threadIdx.x] = W[(size_t)(y0 + threadIdx.y + i * 8) * cHS + x];
    __syncthreads();
    int nx = blockIdx.y * 32 + threadIdx.x;
    int ny0 = blockIdx.x * 32;
#pragma unroll
    for (int i = 0; i < 4; i++) {
        float vv = tile[threadIdx.x][threadIdx.y + i * 8];
        __nv_bfloat16 h, l;
        split1(vv, h, l);
        size_t off = (size_t)(ny0 + threadIdx.y + i * 8) * cHS + nx;
        Oh[off] = h; Ol[off] = l;
    }
}

// ===========================================================================
// transpose_split_v: g_V [bh][s][d] fp32 -> g_Vth/g_Vtl [bh][d][s] bf16
// grid (s/32, d/32, bh), block (32,8)
// ===========================================================================
__global__ void transpose_split_v()
{
    __shared__ float tile[32][33];
    const int bh = blockIdx.z, s0 = blockIdx.x * 32, d0 = blockIdx.y * 32;
    const float* src = g_V + (size_t)bh * cS * cHD;
#pragma unroll
    for (int i = 0; i < 4; i++)
        tile[threadIdx.y + i * 8][threadIdx.x] =
            src[(size_t)(s0 + threadIdx.y + i * 8) * cHD + d0 + threadIdx.x];
    __syncthreads();
    __nv_bfloat16* dh = g_Vth + (size_t)bh * cHD * cS;
    __nv_bfloat16* dl = g_Vtl + (size_t)bh * cHD * cS;
#pragma unroll
    for (int i = 0; i < 4; i++) {
        float vv = tile[threadIdx.x][threadIdx.y + i * 8];
        __nv_bfloat16 h, l;
        split1(vv, h, l);
        size_t off = (size_t)(d0 + threadIdx.y + i * 8) * cS + s0 + threadIdx.x;
        dh[off] = h; dl[off] = l;
    }
}

// ===========================================================================
// gemm_qkv: A/B pre-split bf16 via cp.async. Epilogue: Q/K split-scatter,
// V fp32 scatter [bh,s,d]. 256 thr, 128x128, K-chunk 32, warps 4x2.
// ===========================================================================
__global__ __launch_bounds__(256)
void gemm_qkv(const float* __restrict__ b0v, const float* __restrict__ b1v,
              const float* __restrict__ b2v)
{
    extern __shared__ char smraw[];
    const int z = blockIdx.z;
    const __nv_bfloat16* Ahg = g_inh + (size_t)z * (cB * cS * cHS);
    const __nv_bfloat16* Alg = g_inl + (size_t)z * (cB * cS * cHS);
    const __nv_bfloat16* Bhg = g_WTh + (size_t)z * cHS * cHS;
    const __nv_bfloat16* Blg = g_WTl + (size_t)z * cHS * cHS;
    const float* bias = z == 0 ? b0v : (z == 1 ? b1v : b2v);

    const int t = threadIdx.x, lane = t & 31, wid = t >> 5;
    const int wm = wid >> 1, wn = wid & 1;
    const int gid = lane >> 2, tig = lane & 3;
    const int m0 = blockIdx.y * 128, n0 = blockIdx.x * 128;

    const uint32_t uS = smem_u32(smraw);
    const uint32_t uAh = uS, uAl = uS + 20480, uBh = uS + 40960, uBl = uS + 61440;
    const uint32_t laneA = ldsmA_off(lane, 80) + (uint32_t)(wm * 32 * 80);
    const uint32_t laneB = ldsmB_off(lane, 80) + (uint32_t)(wn * 64 * 80);

    float c[2][8][4] = {};

    // chunk 0
#pragma unroll
    for (int i = 0; i < 2; i++) {
        int idx = t + i * 256, r = idx >> 2, kq = idx & 3;
        uint32_t d = r * 80 + kq * 16;
        size_t sa = (size_t)(m0 + r) * 1024 + kq * 8;
        size_t sb = (size_t)(n0 + r) * 1024 + kq * 8;
        CP_ASYNC16(uAh + d, Ahg + sa);
        CP_ASYNC16(uAl + d, Alg + sa);
        CP_ASYNC16(uBh + d, Bhg + sb);
        CP_ASYNC16(uBl + d, Blg + sb);
    }
    CP_COMMIT();

    const int T = 32;
    for (int ch = 0; ch < T; ch++) {
        const int cur = ch & 1;
        if (ch + 1 < T) {
            const uint32_t bo = (uint32_t)((cur ^ 1)) * 10240;
#pragma unroll
            for (int i = 0; i < 2; i++) {
                int idx = t + i * 256, r = idx >> 2, kq = idx & 3;
                uint32_t d = bo + r * 80 + kq * 16;
                size_t sa = (size_t)(m0 + r) * 1024 + (ch + 1) * 32 + kq * 8;
                size_t sb = (size_t)(n0 + r) * 1024 + (ch + 1) * 32 + kq * 8;
                CP_ASYNC16(uAh + d, Ahg + sa);
                CP_ASYNC16(uAl + d, Alg + sa);
                CP_ASYNC16(uBh + d, Bhg + sb);
                CP_ASYNC16(uBl + d, Blg + sb);
            }
            CP_COMMIT();
            CP_WAIT(1);
        } else {
            CP_WAIT(0);
        }
        __syncthreads();

        const uint32_t bufo = (uint32_t)cur * 10240;
#pragma unroll
        for (int kk = 0; kk < 2; kk++) {
            uint32_t ah[2][4], al[2][4], bh[8][2], bl[8][2];
            const uint32_t ko = (uint32_t)kk * 32;
#pragma unroll
            for (int mi = 0; mi < 2; mi++) {
                uint32_t ao = bufo + laneA + (uint32_t)(mi * 16 * 80) + ko;
                ldsm_x4(ah[mi][0], ah[mi][1], ah[mi][2], ah[mi][3], uAh + ao);
                ldsm_x4(al[mi][0], al[mi][1], al[mi][2], al[mi][3], uAl + ao);
            }
#pragma unroll
            for (int p = 0; p < 4; p++) {
                uint32_t bo2 = bufo + laneB + (uint32_t)(p * 16 * 80) + ko;
                ldsm_x4(bh[2*p][0], bh[2*p][1], bh[2*p+1][0], bh[2*p+1][1], uBh + bo2);
                ldsm_x4(bl[2*p][0], bl[2*p][1], bl[2*p+1][0], bl[2*p+1][1], uBl + bo2);
            }
#pragma unroll
            for (int mi = 0; mi < 2; mi++)
#pragma unroll
                for (int ni = 0; ni < 8; ni++) {
                    mma_bf16(c[mi][ni], al[mi], bh[ni]);
                    mma_bf16(c[mi][ni], ah[mi], bl[ni]);
                    mma_bf16(c[mi][ni], ah[mi], bh[ni]);
                }
        }
        __syncthreads();
    }

#pragma unroll
    for (int mi = 0; mi < 2; mi++)
#pragma unroll
        for (int half = 0; half < 2; half++) {
            int m = m0 + wm * 32 + mi * 16 + gid + half * 8;
            int b = m >> 11, s = m & 2047;
#pragma unroll
            for (int ni = 0; ni < 8; ni++) {
                int n = n0 + wn * 64 + ni * 8 + tig * 2;
                int h = n >> 6, d = n & 63;
                float vx = c[mi][ni][half * 2 + 0] + bias[n];
                float vy = c[mi][ni][half * 2 + 1] + bias[n + 1];
                size_t off = ((size_t)(b * cNH + h) * cS + s) * cHD + d;
                if (z < 2) {
                    __nv_bfloat16 hx, lx, hy, ly;
                    split1(vx, hx, lx);
                    split1(vy, hy, ly);
                    __nv_bfloat16* H = z == 0 ? g_Qh : g_Kh;
                    __nv_bfloat16* L = z == 0 ? g_Ql : g_Kl;
                    *(uint32_t*)&H[off] = pk2(hx, hy);
                    *(uint32_t*)&L[off] = pk2(lx, ly);
                } else {
                    *(float2*)&g_V[off] = make_float2(vx, vy);
                }
            }
        }
}

// ===========================================================================
// gemm_out: A = pre-split ctx, B = pre-split WT[3]; plain fp32 store.
// ===========================================================================
__global__ __launch_bounds__(256)
void gemm_out(const float* __restrict__ bias, float* __restrict__ C)
{
    extern __shared__ char smraw[];
    const __nv_bfloat16* Ahg = g_ctxh;
    const __nv_bfloat16* Alg = g_ctxl;
    const __nv_bfloat16* Bhg = g_WTh + 3L * cHS * cHS;
    const __nv_bfloat16* Blg = g_WTl + 3L * cHS * cHS;

    const int t = threadIdx.x, lane = t & 31, wid = t >> 5;
    const int wm = wid >> 1, wn = wid & 1;
    const int gid = lane >> 2, tig = lane & 3;
    const int m0 = blockIdx.y * 128, n0 = blockIdx.x * 128;

    const uint32_t uS = smem_u32(smraw);
    const uint32_t uAh = uS, uAl = uS + 20480, uBh = uS + 40960, uBl = uS + 61440;
    const uint32_t laneA = ldsmA_off(lane, 80) + (uint32_t)(wm * 32 * 80);
    const uint32_t laneB = ldsmB_off(lane, 80) + (uint32_t)(wn * 64 * 80);

    float c[2][8][4] = {};

#pragma unroll
    for (int i = 0; i < 2; i++) {
        int idx = t + i * 256, r = idx >> 2, kq = idx & 3;
        uint32_t d = r * 80 + kq * 16;
        size_t sa = (size_t)(m0 + r) * 1024 + kq * 8;
        size_t sb = (size_t)(n0 + r) * 1024 + kq * 8;
        CP_ASYNC16(uAh + d, Ahg + sa);
        CP_ASYNC16(uAl + d, Alg + sa);
        CP_ASYNC16(uBh + d, Bhg + sb);
        CP_ASYNC16(uBl + d, Blg + sb);
    }
    CP_COMMIT();

    const int T = 32;
    for (int ch = 0; ch < T; ch++) {
        const int cur = ch & 1;
        if (ch + 1 < T) {
            const uint32_t bo = (uint32_t)((cur ^ 1)) * 10240;
#pragma unroll
            for (int i = 0; i < 2; i++) {
                int idx = t + i * 256, r = idx >> 2, kq = idx & 3;
                uint32_t d = bo + r * 80 + kq * 16;
                size_t sa = (size_t)(m0 + r) * 1024 + (ch + 1) * 32 + kq * 8;
                size_t sb = (size_t)(n0 + r) * 1024 + (ch + 1) * 32 + kq * 8;
                CP_ASYNC16(uAh + d, Ahg + sa);
                CP_ASYNC16(uAl + d, Alg + sa);
                CP_ASYNC16(uBh + d, Bhg + sb);
                CP_ASYNC16(uBl + d, Blg + sb);
            }
            CP_COMMIT();
            CP_WAIT(1);
        } else {
            CP_WAIT(0);
        }
        __syncthreads();

        const uint32_t bufo = (uint32_t)cur * 10240;
#pragma unroll
        for (int kk = 0; kk < 2; kk++) {
            uint32_t ah[2][4], al[2][4], bh[8][2], bl[8][2];
            const uint32_t ko = (uint32_t)kk * 32;
#pragma unroll
            for (int mi = 0; mi < 2; mi++) {
                uint32_t ao = bufo + laneA + (uint32_t)(mi * 16 * 80) + ko;
                ldsm_x4(ah[mi][0], ah[mi][1], ah[mi][2], ah[mi][3], uAh + ao);
                ldsm_x4(al[mi][0], al[mi][1], al[mi][2], al[mi][3], uAl + ao);
            }
#pragma unroll
            for (int p = 0; p < 4; p++) {
                uint32_t bo2 = bufo + laneB + (uint32_t)(p * 16 * 80) + ko;
                ldsm_x4(bh[2*p][0], bh[2*p][1], bh[2*p+1][0], bh[2*p+1][1], uBh + bo2);
                ldsm_x4(bl[2*p][0], bl[2*p][1], bl[2*p+1][0], bl[2*p+1][1], uBl + bo2);
            }
#pragma unroll
            for (int mi = 0; mi < 2; mi++)
#pragma unroll
                for (int ni = 0; ni < 8; ni++) {
                    mma_bf16(c[mi][ni], al[mi], bh[ni]);
                    mma_bf16(c[mi][ni], ah[mi], bl[ni]);
                    mma_bf16(c[mi][ni], ah[mi], bh[ni]);
                }
        }
        __syncthreads();
    }

#pragma unroll
    for (int mi = 0; mi < 2; mi++)
#pragma unroll
        for (int half = 0; half < 2; half++) {
            int m = m0 + wm * 32 + mi * 16 + gid + half * 8;
#pragma unroll
            for (int ni = 0; ni < 8; ni++) {
                int n = n0 + wn * 64 + ni * 8 + tig * 2;
                float2 v;
                v.x = c[mi][ni][half * 2 + 0] + bias[n];
                v.y = c[mi][ni][half * 2 + 1] + bias[n + 1];
                *(float2*)&C[(size_t)m * 1024 + n] = v;
            }
        }
}

// ===========================================================================
// scores_mma: pre-split Q/K via cp.async (stride 144B). Raw masked scores +
// LSE partials. 256 thr, warps 4x2, warp tile 32x64.
// ===========================================================================
__global__ __launch_bounds__(256)
void scores_mma(const int* __restrict__ mask, float* __restrict__ attn)
{
    extern __shared__ char smraw[];
    __shared__ float s_m[128][2];
    __shared__ float s_s[128][2];
    const int t = threadIdx.x, lane = t & 31, wid = t >> 5;
    const int wm = wid >> 1, wn = wid & 1;
    const int gid = lane >> 2, tig = lane & 3;
    const int bh = blockIdx.z, b = bh >> 4;
    const int q0 = blockIdx.y * 128, n0 = blockIdx.x * 128;

    const __nv_bfloat16* Qhg = g_Qh + (size_t)bh * cS * cHD;
    const __nv_bfloat16* Qlg = g_Ql + (size_t)bh * cS * cHD;
    const __nv_bfloat16* Khg = g_Kh + (size_t)bh * cS * cHD;
    const __nv_bfloat16* Klg = g_Kl + (size_t)bh * cS * cHD;

    const uint32_t uS = smem_u32(smraw);
    const uint32_t uQh = uS, uQl = uS + 18432, uKh = uS + 36864, uKl = uS + 55296;
    const uint32_t laneA = ldsmA_off(lane, 144) + (uint32_t)(wm * 32 * 144);
    const uint32_t laneB = ldsmB_off(lane, 144) + (uint32_t)(wn * 64 * 144);

#pragma unroll
    for (int i = 0; i < 4; i++) {
        int idx = t + i * 256, r = idx >> 3, kq = idx & 7;
        uint32_t d = r * 144 + kq * 16;
        size_t sq = (size_t)(q0 + r) * 64 + kq * 8;
        size_t sk = (size_t)(n0 + r) * 64 + kq * 8;
        CP_ASYNC16(uQh + d, Qhg + sq);
        CP_ASYNC16(uQl + d, Qlg + sq);
        CP_ASYNC16(uKh + d, Khg + sk);
        CP_ASYNC16(uKl + d, Klg + sk);
    }
    CP_COMMIT();
    CP_WAIT(0);
    __syncthreads();

    float c[2][8][4] = {};
#pragma unroll
    for (int kk = 0; kk < 4; kk++) {
        uint32_t ah[2][4], al[2][4], bh2[8][2], bl2[8][2];
        const uint32_t ko = (uint32_t)kk * 32;
#pragma unroll
        for (int mi = 0; mi < 2; mi++) {
            uint32_t ao = laneA + (uint32_t)(mi * 16 * 144) + ko;
            ldsm_x4(ah[mi][0], ah[mi][1], ah[mi][2], ah[mi][3], uQh + ao);
            ldsm_x4(al[mi][0], al[mi][1], al[mi][2], al[mi][3], uQl + ao);
        }
#pragma unroll
        for (int p = 0; p < 4; p++) {
            uint32_t bo = laneB + (uint32_t)(p * 16 * 144) + ko;
            ldsm_x4(bh2[2*p][0], bh2[2*p][1], bh2[2*p+1][0], bh2[2*p+1][1], uKh + bo);
            ldsm_x4(bl2[2*p][0], bl2[2*p][1], bl2[2*p+1][0], bl2[2*p+1][1], uKl + bo);
        }
#pragma unroll
        for (int mi = 0; mi < 2; mi++)
#pragma unroll
            for (int ni = 0; ni < 8; ni++) {
                mma_bf16(c[mi][ni], al[mi], bh2[ni]);
                mma_bf16(c[mi][ni], ah[mi], bl2[ni]);
                mma_bf16(c[mi][ni], ah[mi], bh2[ni]);
            }
    }

    const float patv = g_pat[bh] * cSCALE;
    const size_t mbase = (size_t)b * cS * cS;
    const size_t abase = (size_t)bh * cS * cS;
#pragma unroll
    for (int mi = 0; mi < 2; mi++)
#pragma unroll
        for (int half = 0; half < 2; half++) {
            int lr = wm * 32 + mi * 16 + half * 8 + gid;
            int q = q0 + lr;
            float vals[16];
            float mx = -CUDART_INF_F;
#pragma unroll
            for (int ni = 0; ni < 8; ni++) {
                int col = n0 + wn * 64 + ni * 8 + tig * 2;
                float2 v;
                v.x = c[mi][ni][half * 2 + 0] * patv;
                v.y = c[mi][ni][half * 2 + 1] * patv;
                int2 mk = *(const int2*)&mask[mbase + (size_t)q * cS + col];
                if (mk.x == 0) v.x = -1e9f;
                if (mk.y == 0) v.y = -1e9f;
                *(float2*)&attn[abase + (size_t)q * cS + col] = v;
                vals[ni * 2] = v.x; vals[ni * 2 + 1] = v.y;
                mx = fmaxf(mx, fmaxf(v.x, v.y));
            }
            mx = fmaxf(mx, __shfl_xor_sync(0xffffffff, mx, 1));
            mx = fmaxf(mx, __shfl_xor_sync(0xffffffff, mx, 2));
            float s = 0.f;
#pragma unroll
            for (int j = 0; j < 16; j++) s += __expf(vals[j] - mx);
            s += __shfl_xor_sync(0xffffffff, s, 1);
            s += __shfl_xor_sync(0xffffffff, s, 2);
            if (tig == 0) { s_m[lr][wn] = mx; s_s[lr][wn] = s; }
        }
    __syncthreads();
    if (t < 128) {
        float m0v = s_m[t][0], m1v = s_m[t][1];
        float s0v = s_s[t][0], s1v = s_s[t][1];
        float M = fmaxf(m0v, m1v);
        float S = s0v * __expf(m0v - M) + s1v * __expf(m1v - M);
        g_pstats[((size_t)bh * cS + q0 + t) * 16 + blockIdx.x] = make_float2(M, S);
    }
}

__global__ __launch_bounds__(256)
void merge_stats()
{
    const int idx = blockIdx.x * 256 + threadIdx.x;
    const float2* ps = &g_pstats[(size_t)idx * 16];
    float M = -CUDART_INF_F;
#pragma unroll
    for (int j = 0; j < 16; j++) M = fmaxf(M, ps[j].x);
    float S = 0.f;
#pragma unroll
    for (int j = 0; j < 16; j++) S += ps[j].y * __expf(ps[j].x - M);
    g_rowstats[idx] = make_float2(M, 1.0f / S);
}

// ===========================================================================
// context_mma (fused softmax): p split in-register; V pre-split via cp.async.
// Block 128x64, K=2048, warps 4x2 (32x32). Epilogue writes pre-split ctx.
// ===========================================================================
__global__ __launch_bounds__(256)
void context_mma(float* attn)
{
    extern __shared__ char smraw[];
    __nv_bfloat16* Ah = (__nv_bfloat16*)smraw;   // [2][128*40]
    __nv_bfloat16* Al = Ah + 2 * 5120;
    __shared__ float sm_m[128], sm_i[128];
    const int t = threadIdx.x, lane = t & 31, wid = t >> 5;
    const int wm = wid >> 1, wn = wid & 1;
    const int gid = lane >> 2, tig = lane & 3;
    const int bh = blockIdx.y, q0 = blockIdx.x * 128;
    const int b = bh >> 4, h = bh & 15;
    float* Am = attn + (size_t)bh * cS * cS;
    const __nv_bfloat16* Vhg = g_Vth + (size_t)bh * cHD * cS;
    const __nv_bfloat16* Vlg = g_Vtl + (size_t)bh * cHD * cS;

    const uint32_t uS = smem_u32(smraw);
    const uint32_t uAh = uS, uAl = uS + 20480, uBh = uS + 40960, uBl = uS + 51200;
    const uint32_t laneA = ldsmA_off(lane, 80) + (uint32_t)(wm * 32 * 80);
    const uint32_t laneB = ldsmB_off(lane, 80) + (uint32_t)(wn * 32 * 80);

    if (t < 128) {
        float2 rs = g_rowstats[(size_t)bh * cS + q0 + t];
        sm_m[t] = rs.x; sm_i[t] = rs.y;
    }

    float c[2][4][4] = {};
    float4 rA[4];

    // chunk 0: V via cp.async (1 piece per thread per half), p via registers
    {
        int r = t >> 2, kq = t & 3;   // r = d 0..63
        uint32_t d = r * 80 + kq * 16;
        size_t sv = (size_t)r * cS + kq * 8;
        CP_ASYNC16(uBh + d, Vhg + sv);
        CP_ASYNC16(uBl + d, Vlg + sv);
    }
    CP_COMMIT();
#pragma unroll
    for (int i = 0; i < 4; i++) {
        int idx = t + i * 256, r = idx >> 3, kq = idx & 7;
        rA[i] = *(const float4*)&Am[(size_t)(q0 + r) * cS + kq * 4];
    }
    __syncthreads();  // sm_m/sm_i visible
#pragma unroll
    for (int i = 0; i < 4; i++) {
        int idx = t + i * 256, r = idx >> 3, kq = idx & 7;
        float mm = sm_m[r], ii = sm_i[r];
        float4 p;
        p.x = __expf(rA[i].x - mm) * ii;
        p.y = __expf(rA[i].y - mm) * ii;
        p.z = __expf(rA[i].z - mm) * ii;
        p.w = __expf(rA[i].w - mm) * ii;
        *(float4*)&Am[(size_t)(q0 + r) * cS + kq * 4] = p;
        uint2 hp, lp;
        split4_pk(p, hp, lp);
        *(uint2*)&Ah[r * 40 + kq * 4] = hp;
        *(uint2*)&Al[r * 40 + kq * 4] = lp;
    }
    CP_WAIT(0);
    __syncthreads();

    const int T = 64;
    for (int ch = 0; ch < T; ch++) {
        const int cur = ch & 1;
        if (ch + 1 < T) {
            {
                int r = t >> 2, kq = t & 3;
                uint32_t d = (uint32_t)((cur ^ 1)) * 5120 + r * 80 + kq * 16;
                size_t sv = (size_t)r * cS + (ch + 1) * 32 + kq * 8;
                CP_ASYNC16(uBh + d, Vhg + sv);
                CP_ASYNC16(uBl + d, Vlg + sv);
            }
            CP_COMMIT();
#pragma unroll
            for (int i = 0; i < 4; i++) {
                int idx = t + i * 256, r = idx >> 3, kq = idx & 7;
                rA[i] = *(const float4*)&Am[(size_t)(q0 + r) * cS + (ch + 1) * 32 + kq * 4];
            }
        }
        const uint32_t bufA = (uint32_t)cur * 10240;
        const uint32_t bufB = (uint32_t)cur * 5120;
#pragma unroll
        for (int kk = 0; kk < 2; kk++) {
            uint32_t ah[2][4], al[2][4], bh2[4][2], bl2[4][2];
            const uint32_t ko = (uint32_t)kk * 32;
#pragma unroll
            for (int mi = 0; mi < 2; mi++) {
                uint32_t ao = bufA + laneA + (uint32_t)(mi * 16 * 80) + ko;
                ldsm_x4(ah[mi][0], ah[mi][1], ah[mi][2], ah[mi][3], uAh + ao);
                ldsm_x4(al[mi][0], al[mi][1], al[mi][2], al[mi][3], uAl + ao);
            }
#pragma unroll
            for (int p = 0; p < 2; p++) {
                uint32_t bo = bufB + laneB + (uint32_t)(p * 16 * 80) + ko;
                ldsm_x4(bh2[2*p][0], bh2[2*p][1], bh2[2*p+1][0], bh2[2*p+1][1], uBh + bo);
                ldsm_x4(bl2[2*p][0], bl2[2*p][1], bl2[2*p+1][0], bl2[2*p+1][1], uBl + bo);
            }
#pragma unroll
            for (int mi = 0; mi < 2; mi++)
#pragma unroll
                for (int ni = 0; ni < 4; ni++) {
                    mma_bf16(c[mi][ni], al[mi], bh2[ni]);
                    mma_bf16(c[mi][ni], ah[mi], bl2[ni]);
                    mma_bf16(c[mi][ni], ah[mi], bh2[ni]);
                }
        }
        __syncthreads();
        if (ch + 1 < T) {
            __nv_bfloat16* Ahw = Ah + (cur ^ 1) * 5120;
            __nv_bfloat16* Alw = Al + (cur ^ 1) * 5120;
#pragma unroll
            for (int i = 0; i < 4; i++) {
                int idx = t + i * 256, r = idx >> 3, kq = idx & 7;
                float mm = sm_m[r], ii = sm_i[r];
                float4 p;
                p.x = __expf(rA[i].x - mm) * ii;
                p.y = __expf(rA[i].y - mm) * ii;
                p.z = __expf(rA[i].z - mm) * ii;
                p.w = __expf(rA[i].w - mm) * ii;
                *(float4*)&Am[(size_t)(q0 + r) * cS + (ch + 1) * 32 + kq * 4] = p;
                uint2 hp, lp;
                split4_pk(p, hp, lp);
                *(uint2*)&Ahw[r * 40 + kq * 4] = hp;
                *(uint2*)&Alw[r * 40 + kq * 4] = lp;
            }
            CP_WAIT(0);
            __syncthreads();
        }
    }

#pragma unroll
    for (int mi = 0; mi < 2; mi++)
#pragma unroll
        for (int half = 0; half < 2; half++) {
            int s = q0 + wm * 32 + mi * 16 + gid + half * 8;
#pragma unroll
            for (int ni = 0; ni < 4; ni++) {
                int n = wn * 32 + ni * 8 + tig * 2;
                float vx = c[mi][ni][half * 2 + 0];
                float vy = c[mi][ni][half * 2 + 1];
                __nv_bfloat16 hx, lx, hy, ly;
                split1(vx, hx, lx);
                split1(vy, hy, ly);
                size_t off = ((size_t)(b * cS + s)) * cHS + h * cHD + n;
                *(uint32_t*)&g_ctxh[off] = pk2(hx, hy);
                *(uint32_t*)&g_ctxl[off] = pk2(lx, ly);
            }
        }
}

// ===========================================================================
// Pattern selector (unchanged)
// ===========================================================================
__global__ void qmean_partial(const float* __restrict__ query)
{
    const int b = blockIdx.y, tile = blockIdx.x;
    const int t = threadIdx.x;
    const int r0 = tile * 128;
    float s1 = 0.f, s2 = 0.f;
    for (int r = 0; r < 128; r++) {
        const float* base = query + ((size_t)b * cS + r0 + r) * cHS;
        s1 += base[t];
        s2 += base[t + 512];
    }
    g_qpart[(b * 16 + tile) * cHS + t] = s1;
    g_qpart[(b * 16 + tile) * cHS + t + 512] = s2;
}

__global__ __launch_bounds__(512)
void pattern_kernel(const float* __restrict__ Wp1, const float* __restrict__ bp1,
                    const float* __restrict__ Wp2, const float* __restrict__ bp2,
                    const float* __restrict__ patterns)
{
    const int b = blockIdx.x;
    const int t = threadIdx.x;
    __shared__ float qm[cHS];
    __shared__ float hb[cHS / 2];
    __shared__ float pw[cNP];
    for (int c = t; c < cHS; c += 512) {
        float s = 0.f;
        for (int p = 0; p < 16; p++) s += g_qpart[(b * 16 + p) * cHS + c];
        qm[c] = s * (1.0f / cS);
    }
    __syncthreads();
    {
        float a = bp1[t];
        for (int c = 0; c < cHS; c++) a += qm[c] * Wp1[c * (cHS / 2) + t];
        hb[t] = fmaxf(a, 0.f);
    }
    __syncthreads();
    __shared__ float lg[cNP];
    if (t < cNP) {
        float a = bp2[t];
        for (int j = 0; j < cHS / 2; j++) a += hb[j] * Wp2[j * cNP + t];
        lg[t] = a;
    }
    __syncthreads();
    if (t == 0) {
        float mx = lg[0];
        for (int p = 1; p < cNP; p++) mx = fmaxf(mx, lg[p]);
        float s = 0.f;
        for (int p = 0; p < cNP; p++) { pw[p] = __expf(lg[p] - mx); s += pw[p]; }
        float inv = 1.0f / s;
        for (int p = 0; p < cNP; p++) pw[p] *= inv;
    }
    __syncthreads();
    if (t < cNH) {
        float a = 0.f;
        for (int p = 0; p < cNP; p++) a += pw[p] * patterns[p * cNH + t];
        g_pat[b * cNH + t] = a;
    }
}

// ===========================================================================
// kernel_launch
// ===========================================================================
extern "C" void kernel_launch(void* const* d_in, const int* in_sizes, int n_in,
                              void* d_out, int out_size)
{
    const float* query = (const float*)d_in[0];
    const float* key   = (const float*)d_in[1];
    const float* value = (const float*)d_in[2];
    const int*   mask  = (const int*)d_in[3];
    const float* Wq  = (const float*)d_in[4];  const float* bq  = (const float*)d_in[5];
    const float* Wk  = (const float*)d_in[6];  const float* bk  = (const float*)d_in[7];
    const float* Wv  = (const float*)d_in[8];  const float* bv  = (const float*)d_in[9];
    const float* Wo  = (const float*)d_in[10]; const float* bo  = (const float*)d_in[11];
    const float* Wp1 = (const float*)d_in[12]; const float* bp1 = (const float*)d_in[13];
    const float* Wp2 = (const float*)d_in[14]; const float* bp2 = (const float*)d_in[15];
    const float* patterns = (const float*)d_in[16];
    float* out = (float*)d_out;

    float* attn;
    if ((long)out_size >= OUT_ELEMS + ATTN_ELEMS) {
        attn = out + OUT_ELEMS;
    } else {
        void* pa;
        cudaGetSymbolAddress(&pa, g_attn_fallback);
        attn = (float*)pa;
    }

    const int SM_GEMM   = 81920;
    const int SM_SCORES = 73728;
    const int SM_CTX    = 61440;
    cudaFuncSetAttribute(gemm_qkv,   cudaFuncAttributeMaxDynamicSharedMemorySize, SM_GEMM);
    cudaFuncSetAttribute(gemm_out,   cudaFuncAttributeMaxDynamicSharedMemorySize, SM_GEMM);
    cudaFuncSetAttribute(scores_mma, cudaFuncAttributeMaxDynamicSharedMemorySize, SM_SCORES);
    cudaFuncSetAttribute(context_mma, cudaFuncAttributeMaxDynamicSharedMemorySize, SM_CTX);

    // 1. pattern selector
    qmean_partial<<<dim3(16, cB), 512>>>(query);
    pattern_kernel<<<cB, 512>>>(Wp1, bp1, Wp2, bp2, patterns);

    // 2. pre-split inputs + weights
    presplit_in<<<dim3(4096, 3), 256>>>(query, key, value);
    transpose_w<<<dim3(32, 32, 4), dim3(32, 8)>>>(Wq, Wk, Wv, Wo);

    // 3. merged QKV projection (pre-split in/out for Q,K; V fp32)
    dim3 gProj(cHS / 128, (cB * cS) / 128, 3);
    gemm_qkv<<<gProj, 256, SM_GEMM>>>(bq, bk, bv);

    // 4. V transpose + split
    transpose_split_v<<<dim3(cS / 32, cHD / 32, cB * cNH), dim3(32, 8)>>>();

    // 5. raw scores + LSE partials
    dim3 gScores(cS / 128, cS / 128, cB * cNH);
    scores_mma<<<gScores, 256, SM_SCORES>>>(mask, attn);

    // 6. merge row stats
    merge_stats<<<(cB * cNH * cS) / 256, 256>>>();

    // 7. fused softmax + context (pre-split ctx epilogue)
    dim3 gCtx(cS / 128, cB * cNH);
    context_mma<<<gCtx, 256, SM_CTX>>>(attn);

    // 8. output projection
    dim3 gOut(cHS / 128, (cB * cS) / 128);
    gemm_out<<<gOut, 256, SM_GEMM>>>(bo, out);
}